// round 15
// baseline (speedup 1.0000x reference)
#include <cuda_runtime.h>
#include <cuda_bf16.h>

// ---------------------------------------------------------------------------
// SageConv: out = relu([x@Wl + bl | (scatter_sum(val*x[col] -> row))@Wn + bn])
// N=100000 nodes, E=1.6M edges, D_IN=D_OUT=128.
//
// Round 15: half-specialized GEMM CTAs. Even CTAs compute the local half
// (x@Wl), odd CTAs the neigh half (agg@Wn). Per-CTA smem = 96KB (one W +
// one 64-row tile) -> 2 CTAs/SM -> 4 warps/SMSP (was 2), doubling latency
// hiding. Lane = 4 rows x 8 cols (splat amortized x4, crossbar < fma).
// Build + pull kernels identical to the 274.3us R11 winner.
// ---------------------------------------------------------------------------

#define NN 100000
#define EE 1600000
#define D 128

__device__ __align__(16) float g_agg[NN * D];
__device__ int g_deg[NN];
__device__ int g_off[NN + 1];
__device__ int g_cur[NN];
__device__ int g_total;
__device__ __align__(8) unsigned long long g_csr[EE];  // hi32=val, lo32=col

// ---------------------------------------------------------------------------
__global__ void k_zero_deg(int n) {
    if (blockIdx.x == 0 && threadIdx.x == 0) g_total = 0;
    for (int i = blockIdx.x * blockDim.x + threadIdx.x; i < n;
         i += gridDim.x * blockDim.x)
        g_deg[i] = 0;
}

__global__ void k_hist(const int* __restrict__ erow, int E) {
    for (int e = blockIdx.x * blockDim.x + threadIdx.x; e < E;
         e += gridDim.x * blockDim.x)
        atomicAdd(&g_deg[__ldg(erow + e)], 1);
}

// block reduce -> 1 atomicAdd base claim -> block scan -> offsets+cursors
__global__ void k_alloc(int n) {
    __shared__ int s[256];
    __shared__ int sbase;
    int t = threadIdx.x;
    int i = blockIdx.x * 256 + t;
    int dg = (i < n) ? g_deg[i] : 0;
    s[t] = dg;
    __syncthreads();
    for (int d = 1; d < 256; d <<= 1) {
        int v = (t >= d) ? s[t - d] : 0;
        __syncthreads();
        s[t] += v;
        __syncthreads();
    }
    if (t == 255) sbase = atomicAdd(&g_total, s[255]);
    __syncthreads();
    if (i < n) {
        int off = sbase + s[t] - dg;
        g_off[i] = off;
        g_cur[i] = off;
    }
}

__global__ void k_bin(const int* __restrict__ erow,
                      const int* __restrict__ ecol,
                      const float* __restrict__ eval_, int E) {
    for (int e = blockIdx.x * blockDim.x + threadIdx.x; e < E;
         e += gridDim.x * blockDim.x) {
        int r = __ldg(erow + e);
        int c = __ldg(ecol + e);
        float v = __ldg(eval_ + e);
        int pos = atomicAdd(&g_cur[r], 1);
        g_csr[pos] = ((unsigned long long)__float_as_uint(v) << 32) | (unsigned)c;
    }
}

// ---------------------------------------------------------------------------
// Pull-style SpMM: one warp per row; 4 independent gathers in flight.
__global__ void __launch_bounds__(256)
k_pull(const float4* __restrict__ x4, int n) {
    const int lane = threadIdx.x & 31;
    const int gwarp = (blockIdx.x * blockDim.x + threadIdx.x) >> 5;
    const int nwarps = (gridDim.x * blockDim.x) >> 5;

    for (int r = gwarp; r < n; r += nwarps) {
        const int beg = __ldg(g_off + r);
        const int end = beg + __ldg(g_deg + r);
        float4 acc = make_float4(0.f, 0.f, 0.f, 0.f);

        int j = beg;
        for (; j + 4 <= end; j += 4) {
            unsigned long long p0 = __ldg(g_csr + j);
            unsigned long long p1 = __ldg(g_csr + j + 1);
            unsigned long long p2 = __ldg(g_csr + j + 2);
            unsigned long long p3 = __ldg(g_csr + j + 3);
            float4 a = __ldg(x4 + (size_t)(unsigned)p0 * 32 + lane);
            float4 b = __ldg(x4 + (size_t)(unsigned)p1 * 32 + lane);
            float4 c = __ldg(x4 + (size_t)(unsigned)p2 * 32 + lane);
            float4 dd = __ldg(x4 + (size_t)(unsigned)p3 * 32 + lane);
            float v0 = __uint_as_float((unsigned)(p0 >> 32));
            float v1 = __uint_as_float((unsigned)(p1 >> 32));
            float v2 = __uint_as_float((unsigned)(p2 >> 32));
            float v3 = __uint_as_float((unsigned)(p3 >> 32));
            acc.x += v0 * a.x; acc.y += v0 * a.y; acc.z += v0 * a.z; acc.w += v0 * a.w;
            acc.x += v1 * b.x; acc.y += v1 * b.y; acc.z += v1 * b.z; acc.w += v1 * b.w;
            acc.x += v2 * c.x; acc.y += v2 * c.y; acc.z += v2 * c.z; acc.w += v2 * c.w;
            acc.x += v3 * dd.x; acc.y += v3 * dd.y; acc.z += v3 * dd.z; acc.w += v3 * dd.w;
        }
        for (; j < end; j++) {
            unsigned long long p = __ldg(g_csr + j);
            float4 a = __ldg(x4 + (size_t)(unsigned)p * 32 + lane);
            float v = __uint_as_float((unsigned)(p >> 32));
            acc.x += v * a.x; acc.y += v * a.y; acc.z += v * a.z; acc.w += v * a.w;
        }
        reinterpret_cast<float4*>(g_agg)[(size_t)r * 32 + lane] = acc;
    }
}

// ---------------------------------------------------------------------------
// Packed fp32x2 FMA (sm_103a): d = a * b + d
#define FMA2(d, a, b) \
    asm("fma.rn.f32x2 %0, %1, %2, %0;" : "+l"(d) : "l"(a), "l"(b))

__device__ __forceinline__ unsigned long long splat2(float v) {
    unsigned long long r;
    asm("mov.b64 %0, {%1, %1};" : "=l"(r) : "f"(v));
    return r;
}

__device__ __forceinline__ float2 unpack2(unsigned long long p) {
    float2 r;
    asm("mov.b64 {%0, %1}, %2;" : "=f"(r.x), "=f"(r.y) : "l"(p));
    return r;
}

// Per-CTA shared: sW (one weight matrix, 64KB) + sT (64-row tile, 32KB)
#define TROWS 64
#define SMEM_BYTES ((D * D + TROWS * D) * 4)   // 98304 B -> 2 CTAs/SM

// CTA parity selects the half. Warp w covers tile rows w*8..w*8+8:
// lanes 0-15 -> rows +0..4, lanes 16-31 -> rows +4..8 (4 rows per lane).
// Lane covers 8 cols (c0 = (lane&15)*8). W-LDS are 2-way broadcast across
// lane groups; splat amortized over 4 FFMA2s.
__global__ void __launch_bounds__(256)
fused_kernel(const float* __restrict__ x,
             const float* __restrict__ Wl,
             const float* __restrict__ bl,
             const float* __restrict__ Wn,
             const float* __restrict__ bn,
             float* __restrict__ out,
             int n) {
    extern __shared__ float sm[];
    float* sW = sm;             // D*D floats
    float* sT = sm + D * D;     // TROWS*D floats

    const int tid = threadIdx.x;
    const int lane = tid & 31;
    const int w = tid >> 5;
    const int half = blockIdx.x & 1;     // 0=local, 1=neigh
    const int lg = lane >> 4;            // row subgroup within warp
    const int li = lane & 15;
    const int c0 = li * 8;
    const int r0 = w * 8 + lg * 4;       // 4 rows per lane

    // Load this half's weight matrix into shared
    {
        const float4* w4 = reinterpret_cast<const float4*>(half ? Wn : Wl);
        float4* sW4 = reinterpret_cast<float4*>(sW);
        for (int i = tid; i < D * D / 4; i += 256) sW4[i] = w4[i];
    }

    const float* bias = half ? bn : bl;
    float4 bb0 = *reinterpret_cast<const float4*>(bias + c0);
    float4 bb1 = *reinterpret_cast<const float4*>(bias + c0 + 4);

    const float4* src4 = half ? reinterpret_cast<const float4*>(g_agg)
                              : reinterpret_cast<const float4*>(x);

    const int ntiles = (n + TROWS - 1) / TROWS;
    const int tstride = gridDim.x >> 1;
    __syncthreads();

    for (int t = blockIdx.x >> 1; t < ntiles; t += tstride) {
        const int row0 = t * TROWS;
        __syncthreads();
        // Load 64-row tile of this CTA's source
        {
            float4* sT4 = reinterpret_cast<float4*>(sT);
            float4 z = make_float4(0.f, 0.f, 0.f, 0.f);
            for (int i = tid; i < TROWS * 32; i += 256) {
                int r = i >> 5, kk = i & 31;
                int gr = row0 + r;
                sT4[i] = (gr < n) ? src4[(size_t)gr * 32 + kk] : z;
            }
        }
        __syncthreads();

        const float* Abase = sT + r0 * D;

        unsigned long long acc[4][4];
#pragma unroll
        for (int r = 0; r < 4; r++)
#pragma unroll
            for (int q = 0; q < 4; q++) acc[r][q] = 0ull;

        for (int k = 0; k < D; k += 4) {
            float4 xr[4];
#pragma unroll
            for (int r = 0; r < 4; r++)
                xr[r] = *reinterpret_cast<const float4*>(Abase + r * D + k);
#pragma unroll
            for (int kk = 0; kk < 4; kk++) {
                ulonglong2 w01 = *reinterpret_cast<const ulonglong2*>(
                    sW + (k + kk) * D + c0);
                ulonglong2 w23 = *reinterpret_cast<const ulonglong2*>(
                    sW + (k + kk) * D + c0 + 4);
#pragma unroll
                for (int r = 0; r < 4; r++) {
                    float xv = reinterpret_cast<const float*>(&xr[r])[kk];
                    unsigned long long xs = splat2(xv);
                    FMA2(acc[r][0], xs, w01.x);
                    FMA2(acc[r][1], xs, w01.y);
                    FMA2(acc[r][2], xs, w23.x);
                    FMA2(acc[r][3], xs, w23.y);
                }
            }
        }

        // Epilogue: bias + relu; lane writes its 8 cols of its half
#pragma unroll
        for (int r = 0; r < 4; r++) {
            int gr = row0 + r0 + r;
            if (gr < n) {
                float2 p0 = unpack2(acc[r][0]);
                float2 p1 = unpack2(acc[r][1]);
                float2 p2 = unpack2(acc[r][2]);
                float2 p3 = unpack2(acc[r][3]);
                float4 o0, o1;
                o0.x = fmaxf(p0.x + bb0.x, 0.f);
                o0.y = fmaxf(p0.y + bb0.y, 0.f);
                o0.z = fmaxf(p1.x + bb0.z, 0.f);
                o0.w = fmaxf(p1.y + bb0.w, 0.f);
                o1.x = fmaxf(p2.x + bb1.x, 0.f);
                o1.y = fmaxf(p2.y + bb1.y, 0.f);
                o1.z = fmaxf(p3.x + bb1.z, 0.f);
                o1.w = fmaxf(p3.y + bb1.w, 0.f);
                float* op = out + (size_t)gr * 256 + half * D + c0;
                __stcs(reinterpret_cast<float4*>(op), o0);
                __stcs(reinterpret_cast<float4*>(op + 4), o1);
            }
        }
    }
}

// ---------------------------------------------------------------------------
extern "C" void kernel_launch(void* const* d_in, const int* in_sizes, int n_in,
                              void* d_out, int out_size) {
    const float* x  = (const float*)d_in[0];
    const int* erow = (const int*)d_in[1];
    const int* ecol = (const int*)d_in[2];
    const float* ev = (const float*)d_in[3];
    const float* Wl = (const float*)d_in[4];
    const float* bl = (const float*)d_in[5];
    const float* Wn = (const float*)d_in[6];
    const float* bn = (const float*)d_in[7];

    const int n = in_sizes[0] / D;   // nodes (100000)
    const int E = in_sizes[1];       // edges (1600000)
    const int nb = (n + 255) / 256;

    // CSR build
    k_zero_deg<<<256, 256>>>(n);
    k_hist<<<1024, 256>>>(erow, E);
    k_alloc<<<nb, 256>>>(n);
    k_bin<<<1024, 256>>>(erow, ecol, ev, E);

    // Pull-style SpMM
    k_pull<<<2048, 256>>>(reinterpret_cast<const float4*>(x), n);

    // Fused dual-GEMM: 296 CTAs (even=local half, odd=neigh half), 2 CTAs/SM
    cudaFuncSetAttribute(fused_kernel,
                         cudaFuncAttributeMaxDynamicSharedMemorySize, SMEM_BYTES);
    fused_kernel<<<296, 256, SMEM_BYTES>>>(x, Wl, bl, Wn, bn, (float*)d_out, n);
}

// round 16
// speedup vs baseline: 1.3549x; 1.3549x over previous
#include <cuda_runtime.h>
#include <cuda_bf16.h>

// ---------------------------------------------------------------------------
// SageConv: out = relu([x@Wl + bl | (scatter_sum(val*x[col] -> row))@Wn + bn])
// N=100000 nodes, E=1.6M edges, D_IN=D_OUT=128.
//
// Round 16 = R11 winner (274.3us) + ONE change: the fused kernel's tile load
// is register-double-buffered (prefetch next tile's 16 float4/thread into
// registers right after smem is released, overlapping LDG latency with the
// compute block). GEMM inner loop / lane mapping untouched (R9/R14/R15
// showed every remap of it loses).
// ---------------------------------------------------------------------------

#define NN 100000
#define EE 1600000
#define D 128

__device__ __align__(16) float g_agg[NN * D];
__device__ int g_deg[NN];
__device__ int g_off[NN + 1];
__device__ int g_cur[NN];
__device__ int g_total;
__device__ __align__(8) unsigned long long g_csr[EE];  // hi32=val, lo32=col

// ---------------------------------------------------------------------------
__global__ void k_zero_deg(int n) {
    if (blockIdx.x == 0 && threadIdx.x == 0) g_total = 0;
    for (int i = blockIdx.x * blockDim.x + threadIdx.x; i < n;
         i += gridDim.x * blockDim.x)
        g_deg[i] = 0;
}

__global__ void k_hist(const int* __restrict__ erow, int E) {
    for (int e = blockIdx.x * blockDim.x + threadIdx.x; e < E;
         e += gridDim.x * blockDim.x)
        atomicAdd(&g_deg[__ldg(erow + e)], 1);
}

// block reduce -> 1 atomicAdd base claim -> block scan -> offsets+cursors
__global__ void k_alloc(int n) {
    __shared__ int s[256];
    __shared__ int sbase;
    int t = threadIdx.x;
    int i = blockIdx.x * 256 + t;
    int dg = (i < n) ? g_deg[i] : 0;
    s[t] = dg;
    __syncthreads();
    for (int d = 1; d < 256; d <<= 1) {
        int v = (t >= d) ? s[t - d] : 0;
        __syncthreads();
        s[t] += v;
        __syncthreads();
    }
    if (t == 255) sbase = atomicAdd(&g_total, s[255]);
    __syncthreads();
    if (i < n) {
        int off = sbase + s[t] - dg;
        g_off[i] = off;
        g_cur[i] = off;
    }
}

__global__ void k_bin(const int* __restrict__ erow,
                      const int* __restrict__ ecol,
                      const float* __restrict__ eval_, int E) {
    for (int e = blockIdx.x * blockDim.x + threadIdx.x; e < E;
         e += gridDim.x * blockDim.x) {
        int r = __ldg(erow + e);
        int c = __ldg(ecol + e);
        float v = __ldg(eval_ + e);
        int pos = atomicAdd(&g_cur[r], 1);
        g_csr[pos] = ((unsigned long long)__float_as_uint(v) << 32) | (unsigned)c;
    }
}

// ---------------------------------------------------------------------------
// Pull-style SpMM: one warp per row; 4 independent gathers in flight.
__global__ void __launch_bounds__(256)
k_pull(const float4* __restrict__ x4, int n) {
    const int lane = threadIdx.x & 31;
    const int gwarp = (blockIdx.x * blockDim.x + threadIdx.x) >> 5;
    const int nwarps = (gridDim.x * blockDim.x) >> 5;

    for (int r = gwarp; r < n; r += nwarps) {
        const int beg = __ldg(g_off + r);
        const int end = beg + __ldg(g_deg + r);
        float4 acc = make_float4(0.f, 0.f, 0.f, 0.f);

        int j = beg;
        for (; j + 4 <= end; j += 4) {
            unsigned long long p0 = __ldg(g_csr + j);
            unsigned long long p1 = __ldg(g_csr + j + 1);
            unsigned long long p2 = __ldg(g_csr + j + 2);
            unsigned long long p3 = __ldg(g_csr + j + 3);
            float4 a = __ldg(x4 + (size_t)(unsigned)p0 * 32 + lane);
            float4 b = __ldg(x4 + (size_t)(unsigned)p1 * 32 + lane);
            float4 c = __ldg(x4 + (size_t)(unsigned)p2 * 32 + lane);
            float4 dd = __ldg(x4 + (size_t)(unsigned)p3 * 32 + lane);
            float v0 = __uint_as_float((unsigned)(p0 >> 32));
            float v1 = __uint_as_float((unsigned)(p1 >> 32));
            float v2 = __uint_as_float((unsigned)(p2 >> 32));
            float v3 = __uint_as_float((unsigned)(p3 >> 32));
            acc.x += v0 * a.x; acc.y += v0 * a.y; acc.z += v0 * a.z; acc.w += v0 * a.w;
            acc.x += v1 * b.x; acc.y += v1 * b.y; acc.z += v1 * b.z; acc.w += v1 * b.w;
            acc.x += v2 * c.x; acc.y += v2 * c.y; acc.z += v2 * c.z; acc.w += v2 * c.w;
            acc.x += v3 * dd.x; acc.y += v3 * dd.y; acc.z += v3 * dd.z; acc.w += v3 * dd.w;
        }
        for (; j < end; j++) {
            unsigned long long p = __ldg(g_csr + j);
            float4 a = __ldg(x4 + (size_t)(unsigned)p * 32 + lane);
            float v = __uint_as_float((unsigned)(p >> 32));
            acc.x += v * a.x; acc.y += v * a.y; acc.z += v * a.z; acc.w += v * a.w;
        }
        reinterpret_cast<float4*>(g_agg)[(size_t)r * 32 + lane] = acc;
    }
}

// ---------------------------------------------------------------------------
// Packed fp32x2 FMA (sm_103a): d = a * b + d
#define FMA2(d, a, b) \
    asm("fma.rn.f32x2 %0, %1, %2, %0;" : "+l"(d) : "l"(a), "l"(b))

__device__ __forceinline__ unsigned long long splat2(float v) {
    unsigned long long r;
    asm("mov.b64 %0, {%1, %1};" : "=l"(r) : "f"(v));
    return r;
}

__device__ __forceinline__ float2 unpack2(unsigned long long p) {
    float2 r;
    asm("mov.b64 {%0, %1}, %2;" : "=f"(r.x), "=f"(r.y) : "l"(p));
    return r;
}

// Shared: sW (Wl|Wn, 128KB) + sT tile (64 rows x + 64 rows agg = 64KB)
#define TROWS 64
#define SMEM_BYTES ((2 * D * D + 2 * TROWS * D) * 4)

// Tile = 64 rows. Warp w -> rows w*8..w*8+8 of the tile.
// Lanes 0-15 -> local half (x rows, Wl); lanes 16-31 -> neigh half (agg, Wn).
// Each lane: 8 rows x 8 cols. Tile loads register-double-buffered.
__global__ void __launch_bounds__(256)
fused_kernel(const float* __restrict__ x,
             const float* __restrict__ Wl,
             const float* __restrict__ bl,
             const float* __restrict__ Wn,
             const float* __restrict__ bn,
             float* __restrict__ out,
             int n) {
    extern __shared__ float sm[];
    float* sW = sm;                 // 2*128*128 floats
    float* sT = sm + 2 * D * D;     // 2*64*128 floats (x rows | agg rows)

    const int tid = threadIdx.x;
    const int lane = tid & 31;
    const int w = tid >> 5;
    const int half = lane >> 4;          // 0=local, 1=neigh
    const int li = lane & 15;
    const int c0 = li * 8;               // 8 cols within the half

    // Load both weight matrices into shared
    {
        const float4* wl4 = reinterpret_cast<const float4*>(Wl);
        const float4* wn4 = reinterpret_cast<const float4*>(Wn);
        float4* sW4 = reinterpret_cast<float4*>(sW);
        for (int i = tid; i < D * D / 4; i += 256) {
            sW4[i] = wl4[i];
            sW4[D * D / 4 + i] = wn4[i];
        }
    }

    const float* Wh = sW + half * (D * D);
    const float* bias = half ? bn : bl;
    float4 bb0 = *reinterpret_cast<const float4*>(bias + c0);
    float4 bb1 = *reinterpret_cast<const float4*>(bias + c0 + 4);

    const float4* x4 = reinterpret_cast<const float4*>(x);
    const float4* a4 = reinterpret_cast<const float4*>(g_agg);

    const int ntiles = (n + TROWS - 1) / TROWS;

    // register prefetch buffers: 8 float4 of x-tile + 8 of agg-tile / thread
    float4 pfx[8], pfa[8];
    const float4 z = make_float4(0.f, 0.f, 0.f, 0.f);

    // prefetch first tile
    int t = blockIdx.x;
    if (t < ntiles) {
        const int row0 = t * TROWS;
#pragma unroll
        for (int j = 0; j < 8; j++) {
            int i = tid + j * 256;             // 0..2047
            int r = i >> 5, kk = i & 31;
            int gr = row0 + r;
            pfx[j] = (gr < n) ? x4[(size_t)gr * 32 + kk] : z;
            pfa[j] = (gr < n) ? a4[(size_t)gr * 32 + kk] : z;
        }
    }
    __syncthreads();  // weights visible

    for (; t < ntiles; t += gridDim.x) {
        const int row0 = t * TROWS;

        // store prefetched tile to smem
        {
            float4* sT4 = reinterpret_cast<float4*>(sT);
#pragma unroll
            for (int j = 0; j < 8; j++) {
                sT4[tid + j * 256] = pfx[j];
                sT4[TROWS * 32 + tid + j * 256] = pfa[j];
            }
        }
        __syncthreads();

        // prefetch NEXT tile into registers (overlaps with compute below)
        const int tn = t + gridDim.x;
        if (tn < ntiles) {
            const int nrow0 = tn * TROWS;
#pragma unroll
            for (int j = 0; j < 8; j++) {
                int i = tid + j * 256;
                int r = i >> 5, kk = i & 31;
                int gr = nrow0 + r;
                pfx[j] = (gr < n) ? x4[(size_t)gr * 32 + kk] : z;
                pfa[j] = (gr < n) ? a4[(size_t)gr * 32 + kk] : z;
            }
        }

        const int r0 = w * 8;  // 8 rows of the 64-row tile per warp
        const float* Arow = sT + half * (TROWS * D) + r0 * D;

        unsigned long long acc[8][4];
#pragma unroll
        for (int r = 0; r < 8; r++)
#pragma unroll
            for (int q = 0; q < 4; q++) acc[r][q] = 0ull;

        for (int k = 0; k < D; k += 4) {
            float4 xr[8];
#pragma unroll
            for (int r = 0; r < 8; r++)
                xr[r] = *reinterpret_cast<const float4*>(Arow + r * D + k);
#pragma unroll
            for (int kk = 0; kk < 4; kk++) {
                ulonglong2 w01 = *reinterpret_cast<const ulonglong2*>(
                    Wh + (k + kk) * D + c0);
                ulonglong2 w23 = *reinterpret_cast<const ulonglong2*>(
                    Wh + (k + kk) * D + c0 + 4);
#pragma unroll
                for (int r = 0; r < 8; r++) {
                    float xv = reinterpret_cast<const float*>(&xr[r])[kk];
                    unsigned long long xs = splat2(xv);
                    FMA2(acc[r][0], xs, w01.x);
                    FMA2(acc[r][1], xs, w01.y);
                    FMA2(acc[r][2], xs, w23.x);
                    FMA2(acc[r][3], xs, w23.y);
                }
            }
        }

        // Epilogue: bias + relu; lane writes its 8 cols in its half
#pragma unroll
        for (int r = 0; r < 8; r++) {
            int gr = row0 + r0 + r;
            if (gr < n) {
                float2 p0 = unpack2(acc[r][0]);
                float2 p1 = unpack2(acc[r][1]);
                float2 p2 = unpack2(acc[r][2]);
                float2 p3 = unpack2(acc[r][3]);
                float4 o0, o1;
                o0.x = fmaxf(p0.x + bb0.x, 0.f);
                o0.y = fmaxf(p0.y + bb0.y, 0.f);
                o0.z = fmaxf(p1.x + bb0.z, 0.f);
                o0.w = fmaxf(p1.y + bb0.w, 0.f);
                o1.x = fmaxf(p2.x + bb1.x, 0.f);
                o1.y = fmaxf(p2.y + bb1.y, 0.f);
                o1.z = fmaxf(p3.x + bb1.z, 0.f);
                o1.w = fmaxf(p3.y + bb1.w, 0.f);
                float* op = out + (size_t)gr * 256 + half * D + c0;
                __stcs(reinterpret_cast<float4*>(op), o0);
                __stcs(reinterpret_cast<float4*>(op + 4), o1);
            }
        }
        __syncthreads();   // compute done before next store overwrites sT
    }
}

// ---------------------------------------------------------------------------
extern "C" void kernel_launch(void* const* d_in, const int* in_sizes, int n_in,
                              void* d_out, int out_size) {
    const float* x  = (const float*)d_in[0];
    const int* erow = (const int*)d_in[1];
    const int* ecol = (const int*)d_in[2];
    const float* ev = (const float*)d_in[3];
    const float* Wl = (const float*)d_in[4];
    const float* bl = (const float*)d_in[5];
    const float* Wn = (const float*)d_in[6];
    const float* bn = (const float*)d_in[7];

    const int n = in_sizes[0] / D;   // nodes (100000)
    const int E = in_sizes[1];       // edges (1600000)
    const int nb = (n + 255) / 256;

    // CSR build
    k_zero_deg<<<256, 256>>>(n);
    k_hist<<<1024, 256>>>(erow, E);
    k_alloc<<<nb, 256>>>(n);
    k_bin<<<1024, 256>>>(erow, ecol, ev, E);

    // Pull-style SpMM
    k_pull<<<2048, 256>>>(reinterpret_cast<const float4*>(x), n);

    // Fused dual-GEMM + bias + relu + concat (persistent grid)
    cudaFuncSetAttribute(fused_kernel,
                         cudaFuncAttributeMaxDynamicSharedMemorySize, SMEM_BYTES);
    fused_kernel<<<148, 256, SMEM_BYTES>>>(x, Wl, bl, Wn, bn, (float*)d_out, n);
}